// round 1
// baseline (speedup 1.0000x reference)
#include <cuda_runtime.h>
#include <math.h>

// Problem dims (fixed by the dataset)
#define BSZ   4096
#define KDIM  1024
#define N4    4096   // 4*H
#define HDIM  1024

// Scratch for the two GEMM outputs (pre-LayerNorm gates).
// __device__ globals: allowed by harness rules (no dynamic alloc).
__device__ float g_gi[(size_t)BSZ * N4];  // input  @ w_i2h + b_i2h
__device__ float g_gh[(size_t)BSZ * N4];  // h_prev @ w_h2h + b_h2h

// ---------------------------------------------------------------------------
// SGEMM: C[M=4096, N=4096] = A[M,1024] @ W[1024,N] + bias
// 128x128 block tile, BK=16, 256 threads, 8x8 per-thread microtile.
// blockIdx.z selects which of the two GEMMs.
// ---------------------------------------------------------------------------
__global__ void __launch_bounds__(256, 2) gemm_bias_kernel(
    const float* __restrict__ A0, const float* __restrict__ W0, const float* __restrict__ bias0,
    const float* __restrict__ A1, const float* __restrict__ W1, const float* __restrict__ bias1)
{
    const bool second = (blockIdx.z != 0);
    const float* __restrict__ A    = second ? A1 : A0;
    const float* __restrict__ W    = second ? W1 : W0;
    const float* __restrict__ bias = second ? bias1 : bias0;
    float* __restrict__ C          = second ? g_gh : g_gi;

    __shared__ float As[16][128];   // [k][m]
    __shared__ float Bs[16][128];   // [k][n]

    const int tid = threadIdx.x;
    const int tx  = tid & 15;       // 0..15 -> output col group
    const int ty  = tid >> 4;       // 0..15 -> output row group
    const int m0  = blockIdx.y * 128;
    const int n0  = blockIdx.x * 128;

    // A-load mapping: 128 rows x 16 cols = 512 float4; 2 per thread
    const int ar = tid >> 2;          // 0..63 (rows ar, ar+64)
    const int ac = (tid & 3) * 4;     // 0,4,8,12
    // W-load mapping: 16 rows x 128 cols = 512 float4; 2 per thread
    const int br = tid >> 5;          // 0..7 (rows br, br+8)
    const int bc = (tid & 31) * 4;    // 0..124

    float acc[8][8];
    #pragma unroll
    for (int i = 0; i < 8; i++)
        #pragma unroll
        for (int j = 0; j < 8; j++)
            acc[i][j] = 0.0f;

    const float* Ap0 = A + (size_t)(m0 + ar) * KDIM + ac;
    const float* Ap1 = A + (size_t)(m0 + ar + 64) * KDIM + ac;
    const float* Wp0 = W + (size_t)br * N4 + n0 + bc;
    const float* Wp1 = W + (size_t)(br + 8) * N4 + n0 + bc;

    for (int k0 = 0; k0 < KDIM; k0 += 16) {
        float4 a0 = *(const float4*)(Ap0 + k0);
        float4 a1 = *(const float4*)(Ap1 + k0);
        float4 b0 = *(const float4*)(Wp0 + (size_t)k0 * N4);
        float4 b1 = *(const float4*)(Wp1 + (size_t)k0 * N4);

        __syncthreads();   // previous tile's compute must finish before overwrite

        As[ac + 0][ar] = a0.x;  As[ac + 1][ar] = a0.y;
        As[ac + 2][ar] = a0.z;  As[ac + 3][ar] = a0.w;
        As[ac + 0][ar + 64] = a1.x;  As[ac + 1][ar + 64] = a1.y;
        As[ac + 2][ar + 64] = a1.z;  As[ac + 3][ar + 64] = a1.w;
        *(float4*)&Bs[br][bc]     = b0;
        *(float4*)&Bs[br + 8][bc] = b1;

        __syncthreads();

        #pragma unroll
        for (int kk = 0; kk < 16; kk++) {
            float4 ta0 = *(const float4*)&As[kk][ty * 8];
            float4 ta1 = *(const float4*)&As[kk][ty * 8 + 4];
            float4 tb0 = *(const float4*)&Bs[kk][tx * 8];
            float4 tb1 = *(const float4*)&Bs[kk][tx * 8 + 4];
            float a[8] = {ta0.x, ta0.y, ta0.z, ta0.w, ta1.x, ta1.y, ta1.z, ta1.w};
            float b[8] = {tb0.x, tb0.y, tb0.z, tb0.w, tb1.x, tb1.y, tb1.z, tb1.w};
            #pragma unroll
            for (int i = 0; i < 8; i++)
                #pragma unroll
                for (int j = 0; j < 8; j++)
                    acc[i][j] = fmaf(a[i], b[j], acc[i][j]);
        }
    }

    // epilogue: add bias, store
    float bv[8];
    #pragma unroll
    for (int j = 0; j < 8; j++) bv[j] = bias[n0 + tx * 8 + j];

    #pragma unroll
    for (int i = 0; i < 8; i++) {
        const int m = m0 + ty * 8 + i;
        float4 o0, o1;
        o0.x = acc[i][0] + bv[0];  o0.y = acc[i][1] + bv[1];
        o0.z = acc[i][2] + bv[2];  o0.w = acc[i][3] + bv[3];
        o1.x = acc[i][4] + bv[4];  o1.y = acc[i][5] + bv[5];
        o1.z = acc[i][6] + bv[6];  o1.w = acc[i][7] + bv[7];
        *(float4*)&C[(size_t)m * N4 + n0 + tx * 8]     = o0;
        *(float4*)&C[(size_t)m * N4 + n0 + tx * 8 + 4] = o1;
    }
}

// ---------------------------------------------------------------------------
// Block-wide sum of a float4 (256 threads = 8 warps)
// ---------------------------------------------------------------------------
__device__ __forceinline__ float4 block_reduce_sum4(float4 v)
{
    __shared__ float4 sbuf[8];
    const int lane = threadIdx.x & 31;
    const int warp = threadIdx.x >> 5;

    #pragma unroll
    for (int o = 16; o > 0; o >>= 1) {
        v.x += __shfl_down_sync(0xffffffffu, v.x, o);
        v.y += __shfl_down_sync(0xffffffffu, v.y, o);
        v.z += __shfl_down_sync(0xffffffffu, v.z, o);
        v.w += __shfl_down_sync(0xffffffffu, v.w, o);
    }
    if (lane == 0) sbuf[warp] = v;
    __syncthreads();
    if (warp == 0) {
        v = (lane < 8) ? sbuf[lane] : make_float4(0.f, 0.f, 0.f, 0.f);
        #pragma unroll
        for (int o = 4; o > 0; o >>= 1) {
            v.x += __shfl_down_sync(0xffffffffu, v.x, o);
            v.y += __shfl_down_sync(0xffffffffu, v.y, o);
            v.z += __shfl_down_sync(0xffffffffu, v.z, o);
            v.w += __shfl_down_sync(0xffffffffu, v.w, o);
        }
        if (lane == 0) sbuf[0] = v;
    }
    __syncthreads();
    float4 res = sbuf[0];
    __syncthreads();   // protect sbuf before next call
    return res;
}

__device__ __forceinline__ float sigmoidf_(float x) {
    return 1.0f / (1.0f + expf(-x));
}

// ---------------------------------------------------------------------------
// Fused LayerNorm(hi) + LayerNorm(hh) + LSTM gates + LayerNorm(c) + h.
// One block (256 threads) per batch row. Strided element ownership
// idx = t + k*256 puts gates (i,f,u,o) of column j=t+k*256 (k<4) in ONE thread.
// ---------------------------------------------------------------------------
__global__ void __launch_bounds__(256) ln_lstm_kernel(
    const float* __restrict__ c_prev,
    const float* __restrict__ g_i2h,  const float* __restrict__ be_i2h,
    const float* __restrict__ g_h2h,  const float* __restrict__ be_h2h,
    const float* __restrict__ g_c,    const float* __restrict__ be_c,
    float* __restrict__ out_h, float* __restrict__ out_c)
{
    const int row = blockIdx.x;
    const int t   = threadIdx.x;
    const float* gi = g_gi + (size_t)row * N4;
    const float* gh = g_gh + (size_t)row * N4;

    float vi[16], vh[16];
    float4 s = make_float4(0.f, 0.f, 0.f, 0.f);   // sum_i, sumsq_i, sum_h, sumsq_h
    #pragma unroll
    for (int k = 0; k < 16; k++) {
        const int idx = t + k * 256;
        vi[k] = gi[idx];
        vh[k] = gh[idx];
        s.x += vi[k]; s.y += vi[k] * vi[k];
        s.z += vh[k]; s.w += vh[k] * vh[k];
    }
    s = block_reduce_sum4(s);

    const float n1  = (float)N4;
    const float mi  = s.x / n1;
    const float mh  = s.z / n1;
    const float var_i = (s.y - n1 * mi * mi) / (n1 - 1.0f);
    const float var_h = (s.w - n1 * mh * mh) / (n1 - 1.0f);
    const float inv_i = 1.0f / (sqrtf(fmaxf(var_i, 0.f)) + 1e-6f);
    const float inv_h = 1.0f / (sqrtf(fmaxf(var_h, 0.f)) + 1e-6f);

    // normalized sum hi + hh
    float sg[16];
    #pragma unroll
    for (int k = 0; k < 16; k++) {
        const int idx = t + k * 256;
        const float ni = g_i2h[idx] * (vi[k] - mi) * inv_i + be_i2h[idx];
        const float nh = g_h2h[idx] * (vh[k] - mh) * inv_h + be_h2h[idx];
        sg[k] = ni + nh;
    }

    // gates: for j = t + k*256 (k<4): i=sg[k], f=sg[k+4], u=sg[k+8], o=sg[k+12]
    float cn[4], og[4];
    float4 cs = make_float4(0.f, 0.f, 0.f, 0.f);  // sum, sumsq of c_new (y,w unused)
    #pragma unroll
    for (int k = 0; k < 4; k++) {
        const int j = t + k * 256;
        const float ig = sg[k];
        const float fg = sg[k + 4];
        const float ug = sg[k + 8];
        og[k]          = sg[k + 12];
        const float cp = c_prev[(size_t)row * HDIM + j];
        cn[k] = cp * sigmoidf_(fg + 1.0f) + tanhf(ug) * sigmoidf_(ig);
        cs.x += cn[k];
        cs.y += cn[k] * cn[k];
    }
    cs = block_reduce_sum4(cs);

    const float n2   = (float)HDIM;
    const float mc   = cs.x / n2;
    const float var_c = (cs.y - n2 * mc * mc) / (n2 - 1.0f);
    const float inv_c = 1.0f / (sqrtf(fmaxf(var_c, 0.f)) + 1e-6f);

    #pragma unroll
    for (int k = 0; k < 4; k++) {
        const int j = t + k * 256;
        const float cval = g_c[j] * (cn[k] - mc) * inv_c + be_c[j];
        out_c[(size_t)row * HDIM + j] = cval;
        out_h[(size_t)row * HDIM + j] = sigmoidf_(og[k]) * tanhf(cval);
    }
}

// ---------------------------------------------------------------------------
extern "C" void kernel_launch(void* const* d_in, const int* in_sizes, int n_in,
                              void* d_out, int out_size)
{
    const float* input  = (const float*)d_in[0];
    const float* h_prev = (const float*)d_in[1];
    const float* c_prev = (const float*)d_in[2];
    const float* w_i2h  = (const float*)d_in[3];
    const float* b_i2h  = (const float*)d_in[4];
    const float* w_h2h  = (const float*)d_in[5];
    const float* b_h2h  = (const float*)d_in[6];
    const float* gi2h   = (const float*)d_in[7];
    const float* bei2h  = (const float*)d_in[8];
    const float* gh2h   = (const float*)d_in[9];
    const float* beh2h  = (const float*)d_in[10];
    const float* gc     = (const float*)d_in[11];
    const float* bec    = (const float*)d_in[12];

    float* out_h = (float*)d_out;                        // h first
    float* out_c = (float*)d_out + (size_t)BSZ * HDIM;   // then c

    dim3 ggrid(N4 / 128, BSZ / 128, 2);
    gemm_bias_kernel<<<ggrid, 256>>>(input, w_i2h, b_i2h, h_prev, w_h2h, b_h2h);
    ln_lstm_kernel<<<BSZ, 256>>>(c_prev, gi2h, bei2h, gh2h, beh2h, gc, bec,
                                 out_h, out_c);
}

// round 3
// speedup vs baseline: 2.3525x; 2.3525x over previous
#include <cuda_runtime.h>
#include <cuda_bf16.h>
#include <math.h>
#include <stdint.h>

// Problem dims (fixed)
#define BSZ   4096
#define KDIM  1024
#define K3    3072      // 3 * KDIM (split-GEMM concatenated K)
#define N4    4096      // 4*H
#define HDIM  1024

// ---------------------------------------------------------------------------
// Device scratch (static, no dynamic allocation)
// ---------------------------------------------------------------------------
__device__ float g_gi[(size_t)BSZ * N4];   // input  @ w_i2h + b_i2h
__device__ float g_gh[(size_t)BSZ * N4];   // h_prev @ w_h2h + b_h2h

// Concatenated split operands:
//   A3[r][0:1024]=A_hi, [1024:2048]=A_lo, [2048:3072]=A_hi
//   W3[n][0:1024]=W_hi, [1024:2048]=W_hi, [2048:3072]=W_lo   (W transposed to [N,K])
// => A3 @ W3^T over K=3072 == A_hi*W_hi + A_lo*W_hi + A_hi*W_lo
__device__ __nv_bfloat16 g_a3[2][(size_t)BSZ * K3];
__device__ __nv_bfloat16 g_w3[2][(size_t)N4 * K3];

// ---------------------------------------------------------------------------
// Base-PTX helpers (legal on compute_103 virtual arch)
// ---------------------------------------------------------------------------
__device__ __forceinline__ uint32_t smem_u32(const void* p) {
    uint32_t a;
    asm("{ .reg .u64 t; cvta.to.shared.u64 t, %1; cvt.u32.u64 %0, t; }" : "=r"(a) : "l"(p));
    return a;
}
__device__ __forceinline__ void cp_async16(uint32_t s, const void* g) {
    asm volatile("cp.async.cg.shared.global [%0], [%1], 16;" :: "r"(s), "l"(g));
}
#define CP_COMMIT() asm volatile("cp.async.commit_group;" ::: "memory")
#define CP_WAIT(n)  asm volatile("cp.async.wait_group %0;" :: "n"(n) : "memory")

__device__ __forceinline__ void ldsm4(uint32_t& r0, uint32_t& r1, uint32_t& r2, uint32_t& r3,
                                      uint32_t addr) {
    asm volatile("ldmatrix.sync.aligned.m8n8.x4.shared.b16 {%0,%1,%2,%3}, [%4];"
                 : "=r"(r0), "=r"(r1), "=r"(r2), "=r"(r3) : "r"(addr));
}
__device__ __forceinline__ void mma_bf16(float* c, const uint32_t* a, const uint32_t* b) {
    asm volatile(
        "mma.sync.aligned.m16n8k16.row.col.f32.bf16.bf16.f32 "
        "{%0,%1,%2,%3}, {%4,%5,%6,%7}, {%8,%9}, {%0,%1,%2,%3};"
        : "+f"(c[0]), "+f"(c[1]), "+f"(c[2]), "+f"(c[3])
        : "r"(a[0]), "r"(a[1]), "r"(a[2]), "r"(a[3]), "r"(b[0]), "r"(b[1]));
}

// ---------------------------------------------------------------------------
// Conversion kernels
// ---------------------------------------------------------------------------
union BF4 { __nv_bfloat162 b2[2]; uint2 u; };

// Activations: one row per block. src row [1024] fp32 -> A3 row [3072] bf16.
__global__ void __launch_bounds__(256) split_act_kernel(
    const float* __restrict__ src0, const float* __restrict__ src1)
{
    const int plane = blockIdx.z;
    const float* __restrict__ src = plane ? src1 : src0;
    __nv_bfloat16* __restrict__ dst = g_a3[plane] + (size_t)blockIdx.x * K3;

    const int k = threadIdx.x * 4;
    float4 v = *(const float4*)(src + (size_t)blockIdx.x * KDIM + k);

    __nv_bfloat16 h0 = __float2bfloat16(v.x), h1 = __float2bfloat16(v.y);
    __nv_bfloat16 h2 = __float2bfloat16(v.z), h3 = __float2bfloat16(v.w);
    float l0 = v.x - __bfloat162float(h0), l1 = v.y - __bfloat162float(h1);
    float l2 = v.z - __bfloat162float(h2), l3 = v.w - __bfloat162float(h3);

    BF4 ph, pl;
    ph.b2[0] = __halves2bfloat162(h0, h1);
    ph.b2[1] = __halves2bfloat162(h2, h3);
    pl.b2[0] = __floats2bfloat162_rn(l0, l1);
    pl.b2[1] = __floats2bfloat162_rn(l2, l3);

    *(uint2*)(dst + k)            = ph.u;   // seg0: hi
    *(uint2*)(dst + KDIM + k)     = pl.u;   // seg1: lo
    *(uint2*)(dst + 2 * KDIM + k) = ph.u;   // seg2: hi (dup)
}

// Weights: W [KDIM, N4] fp32 -> W3 [N4, 3072] bf16 (transpose + split)
__global__ void __launch_bounds__(256) split_wt_kernel(
    const float* __restrict__ w0, const float* __restrict__ w1)
{
    const int plane = blockIdx.z;
    const float* __restrict__ W = plane ? w1 : w0;
    __nv_bfloat16* __restrict__ D = g_w3[plane];

    __shared__ float tile[32][33];
    const int tx = threadIdx.x;          // 0..31
    const int ty = threadIdx.y;          // 0..7
    const int n0 = blockIdx.x * 32;      // N tile
    const int k0 = blockIdx.y * 32;      // K tile

    #pragma unroll
    for (int j = 0; j < 4; j++) {
        const int k = k0 + ty + j * 8;
        tile[ty + j * 8][tx] = W[(size_t)k * N4 + n0 + tx];
    }
    __syncthreads();
    #pragma unroll
    for (int j = 0; j < 4; j++) {
        const int n = n0 + ty + j * 8;
        const float v = tile[tx][ty + j * 8];     // = W[k0+tx][n]
        __nv_bfloat16 h = __float2bfloat16(v);
        const float lo = v - __bfloat162float(h);
        __nv_bfloat16* row = D + (size_t)n * K3 + k0 + tx;
        row[0]        = h;                       // seg0: hi
        row[KDIM]     = h;                       // seg1: hi
        row[2 * KDIM] = __float2bfloat16(lo);    // seg2: lo
    }
}

// ---------------------------------------------------------------------------
// bf16 mma.sync GEMM: C[4096, 4096] = A3[4096,3072] @ W3[4096,3072]^T + bias
// CTA tile 128x256, BK=32, 8 warps (2x4), warp tile 64x64, 3-stage cp.async.
// ---------------------------------------------------------------------------
#define BM 128
#define BN 256
#define BK 32
#define STAGES 3
#define A_ST ((BM) * (BK) * 2)                  // 8192 B
#define B_ST ((BN) * (BK) * 2)                  // 16384 B
#define STAGE_BYTES (A_ST + B_ST)               // 24576 B
#define GEMM_SMEM (STAGES * STAGE_BYTES)        // 73728 B
#define ITERS (K3 / BK)                         // 96

// smem element [r][k] (k in 0..31 bf16): 4 chunks of 16B per 64B row,
// chunk' = chunk ^ ((r>>1)&3) — conflict-free for ldmatrix 8-row phases.
__device__ __forceinline__ uint32_t sw_off(int r, int chunk) {
    return (uint32_t)(r * 64 + ((chunk ^ ((r >> 1) & 3)) << 4));
}

__device__ __forceinline__ void load_stage(
    uint32_t sA, uint32_t sB,
    const __nv_bfloat16* __restrict__ Ag, const __nv_bfloat16* __restrict__ Wg,
    int m0, int n0, int kt, int tid)
{
    const int kbase = kt * BK;
    #pragma unroll
    for (int i = 0; i < 2; i++) {                 // A: 512 chunks / 256 thr
        const int id = tid + i * 256;
        const int r = id >> 2, kc = id & 3;
        cp_async16(sA + sw_off(r, kc), Ag + (size_t)(m0 + r) * K3 + kbase + kc * 8);
    }
    #pragma unroll
    for (int i = 0; i < 4; i++) {                 // B: 1024 chunks / 256 thr
        const int id = tid + i * 256;
        const int r = id >> 2, kc = id & 3;
        cp_async16(sB + sw_off(r, kc), Wg + (size_t)(n0 + r) * K3 + kbase + kc * 8);
    }
}

__global__ void __launch_bounds__(256, 1) gemm_mma_kernel(
    const float* __restrict__ bias0, const float* __restrict__ bias1)
{
    extern __shared__ char smem[];
    const uint32_t sbase = smem_u32(smem);
    const int tid  = threadIdx.x;
    const int lane = tid & 31;
    const int wid  = tid >> 5;
    const int wm   = wid >> 2;     // 0..1 -> m offset 64*wm
    const int wn   = wid & 3;      // 0..3 -> n offset 64*wn

    const int gemm = blockIdx.z;
    const int m0 = blockIdx.y * BM;
    const int n0 = blockIdx.x * BN;

    const __nv_bfloat16* __restrict__ Ag = g_a3[gemm];
    const __nv_bfloat16* __restrict__ Wg = g_w3[gemm];
    float* __restrict__ C = gemm ? g_gh : g_gi;
    const float* __restrict__ bias = gemm ? bias1 : bias0;

    float acc[4][8][4];
    #pragma unroll
    for (int i = 0; i < 4; i++)
        #pragma unroll
        for (int j = 0; j < 8; j++)
            #pragma unroll
            for (int r = 0; r < 4; r++)
                acc[i][j][r] = 0.0f;

    // ldmatrix per-lane addressing components
    const int row_a  = lane & 15;              // A: rows lanes 0..15
    const int ksel_a = lane >> 4;              // A: k-half select
    const int row_b  = ((lane >> 4) << 3) | (lane & 7);  // B: n row
    const int ksel_b = (lane >> 3) & 1;        // B: k-half select

    // prefetch stages 0,1
    load_stage(sbase, sbase + A_ST, Ag, Wg, m0, n0, 0, tid);
    CP_COMMIT();
    load_stage(sbase + STAGE_BYTES, sbase + STAGE_BYTES + A_ST, Ag, Wg, m0, n0, 1, tid);
    CP_COMMIT();

    #pragma unroll 1
    for (int kt = 0; kt < ITERS; kt++) {
        CP_WAIT(1);
        __syncthreads();
        const int s = kt % STAGES;
        const uint32_t sA = sbase + s * STAGE_BYTES;
        const uint32_t sB = sA + A_ST;

        #pragma unroll
        for (int ks = 0; ks < 2; ks++) {
            uint32_t a[4][4], b[4][4];
            #pragma unroll
            for (int mt = 0; mt < 4; mt++) {
                const int r = wm * 64 + mt * 16 + row_a;
                ldsm4(a[mt][0], a[mt][1], a[mt][2], a[mt][3],
                      sA + sw_off(r, ks * 2 + ksel_a));
            }
            #pragma unroll
            for (int bt = 0; bt < 4; bt++) {
                const int n = wn * 64 + bt * 16 + row_b;
                ldsm4(b[bt][0], b[bt][1], b[bt][2], b[bt][3],
                      sB + sw_off(n, ks * 2 + ksel_b));
            }
            #pragma unroll
            for (int mt = 0; mt < 4; mt++)
                #pragma unroll
                for (int bt = 0; bt < 4; bt++) {
                    mma_bf16(acc[mt][bt * 2],     a[mt], &b[bt][0]);
                    mma_bf16(acc[mt][bt * 2 + 1], a[mt], &b[bt][2]);
                }
        }

        if (kt + 2 < ITERS) {
            const int sn = (kt + 2) % STAGES;
            load_stage(sbase + sn * STAGE_BYTES, sbase + sn * STAGE_BYTES + A_ST,
                       Ag, Wg, m0, n0, kt + 2, tid);
        }
        CP_COMMIT();
    }

    // epilogue: bias add + store fp32
    float2 bv[8];
    #pragma unroll
    for (int nf = 0; nf < 8; nf++) {
        const int n = n0 + wn * 64 + nf * 8 + (lane & 3) * 2;
        bv[nf] = *(const float2*)(bias + n);
    }
    #pragma unroll
    for (int mt = 0; mt < 4; mt++) {
        const int m = m0 + wm * 64 + mt * 16 + (lane >> 2);
        #pragma unroll
        for (int nf = 0; nf < 8; nf++) {
            const int n = n0 + wn * 64 + nf * 8 + (lane & 3) * 2;
            float2 o0, o1;
            o0.x = acc[mt][nf][0] + bv[nf].x;
            o0.y = acc[mt][nf][1] + bv[nf].y;
            o1.x = acc[mt][nf][2] + bv[nf].x;
            o1.y = acc[mt][nf][3] + bv[nf].y;
            *(float2*)&C[(size_t)m * N4 + n]       = o0;
            *(float2*)&C[(size_t)(m + 8) * N4 + n] = o1;
        }
    }
}

// ---------------------------------------------------------------------------
// Fused LayerNorm + LSTM gate kernel (unchanged from passing baseline)
// ---------------------------------------------------------------------------
__device__ __forceinline__ float4 block_reduce_sum4(float4 v)
{
    __shared__ float4 sbuf[8];
    const int lane = threadIdx.x & 31;
    const int warp = threadIdx.x >> 5;
    #pragma unroll
    for (int o = 16; o > 0; o >>= 1) {
        v.x += __shfl_down_sync(0xffffffffu, v.x, o);
        v.y += __shfl_down_sync(0xffffffffu, v.y, o);
        v.z += __shfl_down_sync(0xffffffffu, v.z, o);
        v.w += __shfl_down_sync(0xffffffffu, v.w, o);
    }
    if (lane == 0) sbuf[warp] = v;
    __syncthreads();
    if (warp == 0) {
        v = (lane < 8) ? sbuf[lane] : make_float4(0.f, 0.f, 0.f, 0.f);
        #pragma unroll
        for (int o = 4; o > 0; o >>= 1) {
            v.x += __shfl_down_sync(0xffffffffu, v.x, o);
            v.y += __shfl_down_sync(0xffffffffu, v.y, o);
            v.z += __shfl_down_sync(0xffffffffu, v.z, o);
            v.w += __shfl_down_sync(0xffffffffu, v.w, o);
        }
        if (lane == 0) sbuf[0] = v;
    }
    __syncthreads();
    float4 res = sbuf[0];
    __syncthreads();
    return res;
}

__device__ __forceinline__ float sigmoidf_(float x) { return 1.0f / (1.0f + expf(-x)); }

__global__ void __launch_bounds__(256) ln_lstm_kernel(
    const float* __restrict__ c_prev,
    const float* __restrict__ g_i2h,  const float* __restrict__ be_i2h,
    const float* __restrict__ g_h2h,  const float* __restrict__ be_h2h,
    const float* __restrict__ g_c,    const float* __restrict__ be_c,
    float* __restrict__ out_h, float* __restrict__ out_c)
{
    const int row = blockIdx.x;
    const int t   = threadIdx.x;
    const float* gi = g_gi + (size_t)row * N4;
    const float* gh = g_gh + (size_t)row * N4;

    float vi[16], vh[16];
    float4 s = make_float4(0.f, 0.f, 0.f, 0.f);
    #pragma unroll
    for (int k = 0; k < 16; k++) {
        const int idx = t + k * 256;
        vi[k] = gi[idx];
        vh[k] = gh[idx];
        s.x += vi[k]; s.y += vi[k] * vi[k];
        s.z += vh[k]; s.w += vh[k] * vh[k];
    }
    s = block_reduce_sum4(s);

    const float n1  = (float)N4;
    const float mi  = s.x / n1;
    const float mh  = s.z / n1;
    const float var_i = (s.y - n1 * mi * mi) / (n1 - 1.0f);
    const float var_h = (s.w - n1 * mh * mh) / (n1 - 1.0f);
    const float inv_i = 1.0f / (sqrtf(fmaxf(var_i, 0.f)) + 1e-6f);
    const float inv_h = 1.0f / (sqrtf(fmaxf(var_h, 0.f)) + 1e-6f);

    float sg[16];
    #pragma unroll
    for (int k = 0; k < 16; k++) {
        const int idx = t + k * 256;
        const float ni = g_i2h[idx] * (vi[k] - mi) * inv_i + be_i2h[idx];
        const float nh = g_h2h[idx] * (vh[k] - mh) * inv_h + be_h2h[idx];
        sg[k] = ni + nh;
    }

    float cn[4], og[4];
    float4 cs = make_float4(0.f, 0.f, 0.f, 0.f);
    #pragma unroll
    for (int k = 0; k < 4; k++) {
        const int j = t + k * 256;
        const float ig = sg[k];
        const float fg = sg[k + 4];
        const float ug = sg[k + 8];
        og[k]          = sg[k + 12];
        const float cp = c_prev[(size_t)row * HDIM + j];
        cn[k] = cp * sigmoidf_(fg + 1.0f) + tanhf(ug) * sigmoidf_(ig);
        cs.x += cn[k];
        cs.y += cn[k] * cn[k];
    }
    cs = block_reduce_sum4(cs);

    const float n2   = (float)HDIM;
    const float mc   = cs.x / n2;
    const float var_c = (cs.y - n2 * mc * mc) / (n2 - 1.0f);
    const float inv_c = 1.0f / (sqrtf(fmaxf(var_c, 0.f)) + 1e-6f);

    #pragma unroll
    for (int k = 0; k < 4; k++) {
        const int j = t + k * 256;
        const float cval = g_c[j] * (cn[k] - mc) * inv_c + be_c[j];
        out_c[(size_t)row * HDIM + j] = cval;
        out_h[(size_t)row * HDIM + j] = sigmoidf_(og[k]) * tanhf(cval);
    }
}

// ---------------------------------------------------------------------------
extern "C" void kernel_launch(void* const* d_in, const int* in_sizes, int n_in,
                              void* d_out, int out_size)
{
    const float* input  = (const float*)d_in[0];
    const float* h_prev = (const float*)d_in[1];
    const float* c_prev = (const float*)d_in[2];
    const float* w_i2h  = (const float*)d_in[3];
    const float* b_i2h  = (const float*)d_in[4];
    const float* w_h2h  = (const float*)d_in[5];
    const float* b_h2h  = (const float*)d_in[6];
    const float* gi2h   = (const float*)d_in[7];
    const float* bei2h  = (const float*)d_in[8];
    const float* gh2h   = (const float*)d_in[9];
    const float* beh2h  = (const float*)d_in[10];
    const float* gc     = (const float*)d_in[11];
    const float* bec    = (const float*)d_in[12];

    float* out_h = (float*)d_out;
    float* out_c = (float*)d_out + (size_t)BSZ * HDIM;

    // conversions: build A3 / W3 split operands
    split_act_kernel<<<dim3(BSZ, 1, 2), 256>>>(input, h_prev);
    split_wt_kernel<<<dim3(N4 / 32, KDIM / 32, 2), dim3(32, 8)>>>(w_i2h, w_h2h);

    // GEMMs on tensor pipe (mma.sync bf16)
    static bool attr_set = false;
    if (!attr_set) {
        cudaFuncSetAttribute(gemm_mma_kernel,
                             cudaFuncAttributeMaxDynamicSharedMemorySize, GEMM_SMEM);
        attr_set = true;
    }
    gemm_mma_kernel<<<dim3(N4 / BN, BSZ / BM, 2), 256, GEMM_SMEM>>>(b_i2h, b_h2h);

    ln_lstm_kernel<<<BSZ, 256>>>(c_prev, gi2h, bei2h, gh2h, beh2h, gc, bec,
                                 out_h, out_c);
}